// round 7
// baseline (speedup 1.0000x reference)
#include <cuda_runtime.h>

#define N_NODES 50000
#define N_EDGES 800000
#define IN_F 64
#define D_ATT 64
#define HEADS 8
#define D_HEAD 8

typedef unsigned long long ull;

// Scratch (device globals — no allocation allowed).
// g_q / g_k are stored TRANSPOSED within each 64-wide row: [node][d*8 + h],
// so each head-dim d's 8 values are contiguous (one 32B span).
__device__ __align__(16) float g_q[N_NODES * D_ATT];
__device__ __align__(16) float g_k[N_NODES * D_ATT];
__device__ __align__(16) float g_sum[N_NODES * D_HEAD];

// ---------- f32x2 helpers (sm_103a packed FFMA2) ----------
__device__ __forceinline__ void unpack2(ull v, float& lo, float& hi) {
    asm("mov.b64 {%0, %1}, %2;" : "=f"(lo), "=f"(hi) : "l"(v));
}
__device__ __forceinline__ ull fma2(ull a, ull b, ull c) {
    ull d;
    asm("fma.rn.f32x2 %0, %1, %2, %3;" : "=l"(d) : "l"(a), "l"(b), "l"(c));
    return d;
}

#define WT_STRIDE 66   // padded row stride (floats) for transposed W in smem
#define XS_STRIDE 66   // padded row stride (floats) for x tile

// Fused Q/K/V projection (+ zeroing of g_sum).
// Block = (64, 4) threads covering 32 rows; all-SMEM inner loop.
// W staged TRANSPOSED in smem (Wt[c][k]); accumulators are f32x2 packed over
// the k axis (even/odd partial dots, horizontal add at the end).
// Thread tx computes weight column oc = perm(tx) so q/k land transposed
// with coalesced stores; v keeps the original layout.
__global__ void proj_kernel(const float* __restrict__ x,
                            const float* __restrict__ Wq, const float* __restrict__ bq,
                            const float* __restrict__ Wk, const float* __restrict__ bk,
                            const float* __restrict__ Wv, const float* __restrict__ bv,
                            float* __restrict__ v_out) {
    extern __shared__ float sm[];
    float* Wq_t = sm;                              // [64][WT_STRIDE]
    float* Wk_t = Wq_t + 64 * WT_STRIDE;
    float* Wv_t = Wk_t + 64 * WT_STRIDE;
    float* xs   = Wv_t + 64 * WT_STRIDE;           // [32][XS_STRIDE]

    const int tx = threadIdx.x;      // 0..63
    const int rg = threadIdx.y;      // 0..3
    const int row0 = blockIdx.x * 32;
    const int tid = rg * 64 + tx;
    const int oc = ((tx & 7) << 3) | (tx >> 3);  // original column (involution)

    // Zero this block's slice of g_sum (1563 blocks x 256 >= 400000 entries)
    {
        int zi = blockIdx.x * 256 + tid;
        if (zi < N_NODES * D_HEAD) g_sum[zi] = 0.0f;
    }

    // Stage W transposed: Wt[c][k] = W[k][c]
    for (int i = tid; i < 64 * 16; i += 256) {
        int k = i >> 4, c4 = (i & 15) << 2;
        float4 wq = __ldg((const float4*)&Wq[k * D_ATT + c4]);
        float4 wk = __ldg((const float4*)&Wk[k * D_ATT + c4]);
        float4 wv = __ldg((const float4*)&Wv[k * D_ATT + c4]);
        Wq_t[(c4 + 0) * WT_STRIDE + k] = wq.x;
        Wq_t[(c4 + 1) * WT_STRIDE + k] = wq.y;
        Wq_t[(c4 + 2) * WT_STRIDE + k] = wq.z;
        Wq_t[(c4 + 3) * WT_STRIDE + k] = wq.w;
        Wk_t[(c4 + 0) * WT_STRIDE + k] = wk.x;
        Wk_t[(c4 + 1) * WT_STRIDE + k] = wk.y;
        Wk_t[(c4 + 2) * WT_STRIDE + k] = wk.z;
        Wk_t[(c4 + 3) * WT_STRIDE + k] = wk.w;
        Wv_t[(c4 + 0) * WT_STRIDE + k] = wv.x;
        Wv_t[(c4 + 1) * WT_STRIDE + k] = wv.y;
        Wv_t[(c4 + 2) * WT_STRIDE + k] = wv.z;
        Wv_t[(c4 + 3) * WT_STRIDE + k] = wv.w;
    }

    // Stage x tile row-major (coalesced read)
    for (int i = tid; i < 32 * IN_F; i += 256) {
        int r = i >> 6, kk = i & 63;
        int grow = row0 + r;
        xs[r * XS_STRIDE + kk] = (grow < N_NODES) ? x[grow * IN_F + kk] : 0.0f;
    }
    __syncthreads();

    ull aq[8], ak[8], av[8];
#pragma unroll
    for (int i = 0; i < 8; i++) { aq[i] = 0ull; ak[i] = 0ull; av[i] = 0ull; }

    const float* wq_row = &Wq_t[oc * WT_STRIDE];
    const float* wk_row = &Wk_t[oc * WT_STRIDE];
    const float* wv_row = &Wv_t[oc * WT_STRIDE];
    const float* x_base = &xs[(rg * 8) * XS_STRIDE];

#pragma unroll 4
    for (int kk2 = 0; kk2 < IN_F / 2; kk2++) {
        ull wq2 = *(const ull*)&wq_row[2 * kk2];   // LDS.64
        ull wk2 = *(const ull*)&wk_row[2 * kk2];
        ull wv2 = *(const ull*)&wv_row[2 * kk2];
#pragma unroll
        for (int i = 0; i < 8; i++) {
            ull x2 = *(const ull*)&x_base[i * XS_STRIDE + 2 * kk2];  // broadcast LDS.64
            aq[i] = fma2(x2, wq2, aq[i]);
            ak[i] = fma2(x2, wk2, ak[i]);
            av[i] = fma2(x2, wv2, av[i]);
        }
    }

    const float bqv = __ldg(&bq[oc]), bkv = __ldg(&bk[oc]), bvv = __ldg(&bv[oc]);
#pragma unroll
    for (int i = 0; i < 8; i++) {
        int r = row0 + rg * 8 + i;
        if (r < N_NODES) {
            float lo, hi;
            unpack2(aq[i], lo, hi);
            g_q[r * D_ATT + tx] = lo + hi + bqv;
            unpack2(ak[i], lo, hi);
            g_k[r * D_ATT + tx] = lo + hi + bkv;
            unpack2(av[i], lo, hi);
            v_out[r * D_ATT + oc] = lo + hi + bvv;
        }
    }
}

// Cooperative edge kernel: 8 lanes per edge.
// Lane j loads the CONTIGUOUS float4 at byte offset j*16 of the q/k rows
// (one 128B line per LDG.128 per edge). Elements j*4..j*4+3 all belong to
// head-dim d = j>>1: 4-wide partial dot + one shfl_xor(1) finishes each dot.
// Lane j then owns one (d, exp): 1 exp, 1 prods store, 1 att store per lane.
// Four shuffles gather the 8 exps into lanes 0/1, which issue two
// red.global.add.v4.f32 into g_sum. Max-subtraction omitted: softmax ratio is
// shift-invariant; logits ~N(0,3) cannot overflow fp32 exp.
__global__ void edge_kernel(const int* __restrict__ e0, const int* __restrict__ e1,
                            float* __restrict__ att_out, float* __restrict__ prods_out) {
    const int idx = blockIdx.x * blockDim.x + threadIdx.x;  // grid exact: N_EDGES*8
    const int e = idx >> 3;
    const int lane = threadIdx.x & 31;
    const int j = lane & 7;
    const int grp = lane & ~7;

    const int s = e0[e];
    const int t = e1[e];

    const float4* qp = (const float4*)(g_q + s * D_ATT);
    const float4* kp = (const float4*)(g_k + t * D_ATT);
    float4 q0 = qp[j];
    float4 q1 = qp[8 + j];
    float4 k0 = kp[j];
    float4 k1 = kp[8 + j];

    float p0 = q0.x * k0.x;
    p0 = fmaf(q0.y, k0.y, p0);
    p0 = fmaf(q0.z, k0.z, p0);
    p0 = fmaf(q0.w, k0.w, p0);
    float p1 = q1.x * k1.x;
    p1 = fmaf(q1.y, k1.y, p1);
    p1 = fmaf(q1.z, k1.z, p1);
    p1 = fmaf(q1.w, k1.w, p1);

    p0 += __shfl_xor_sync(0xffffffffu, p0, 1);
    p1 += __shfl_xor_sync(0xffffffffu, p1, 1);

    const float c = 0.35355339059327373f;  // 1/sqrt(8)
    const int m = j >> 1;
    const int odd = j & 1;
    const int d = odd ? (4 + m) : m;
    const float p = (odd ? p1 : p0) * c;

    const int oidx = e * D_HEAD + d;
    prods_out[oidx] = p;
    const float ex = __expf(p);
    att_out[oidx] = ex;

    float r0 = __shfl_sync(0xffffffffu, ex, grp + odd);
    float r1 = __shfl_sync(0xffffffffu, ex, grp + odd + 2);
    float r2 = __shfl_sync(0xffffffffu, ex, grp + odd + 4);
    float r3 = __shfl_sync(0xffffffffu, ex, grp + odd + 6);
    if (j < 2) {
        float* dst = &g_sum[t * D_HEAD + j * 4];  // 16B aligned
        asm volatile("red.global.add.v4.f32 [%0], {%1, %2, %3, %4};"
                     :: "l"(dst), "f"(r0), "f"(r1), "f"(r2), "f"(r3)
                     : "memory");
    }
}

// Two adjacent edges per thread: int2 index load, 4 independent sum-gather
// LDG.128 in flight.
__global__ void norm_kernel(const int* __restrict__ e1, float* __restrict__ att) {
    int i = blockIdx.x * blockDim.x + threadIdx.x;
    if (i >= N_EDGES / 2) return;
    int2 tt = ((const int2*)e1)[i];
    float4* att4 = (float4*)att;
    const float4* sum4 = (const float4*)g_sum;
    float4 sa0 = sum4[tt.x * 2], sa1 = sum4[tt.x * 2 + 1];
    float4 sb0 = sum4[tt.y * 2], sb1 = sum4[tt.y * 2 + 1];
    float4 a0 = att4[i * 4 + 0], a1 = att4[i * 4 + 1];
    float4 b0 = att4[i * 4 + 2], b1 = att4[i * 4 + 3];
    a0.x = __fdividef(a0.x, sa0.x + 1e-16f);
    a0.y = __fdividef(a0.y, sa0.y + 1e-16f);
    a0.z = __fdividef(a0.z, sa0.z + 1e-16f);
    a0.w = __fdividef(a0.w, sa0.w + 1e-16f);
    a1.x = __fdividef(a1.x, sa1.x + 1e-16f);
    a1.y = __fdividef(a1.y, sa1.y + 1e-16f);
    a1.z = __fdividef(a1.z, sa1.z + 1e-16f);
    a1.w = __fdividef(a1.w, sa1.w + 1e-16f);
    b0.x = __fdividef(b0.x, sb0.x + 1e-16f);
    b0.y = __fdividef(b0.y, sb0.y + 1e-16f);
    b0.z = __fdividef(b0.z, sb0.z + 1e-16f);
    b0.w = __fdividef(b0.w, sb0.w + 1e-16f);
    b1.x = __fdividef(b1.x, sb1.x + 1e-16f);
    b1.y = __fdividef(b1.y, sb1.y + 1e-16f);
    b1.z = __fdividef(b1.z, sb1.z + 1e-16f);
    b1.w = __fdividef(b1.w, sb1.w + 1e-16f);
    att4[i * 4 + 0] = a0;
    att4[i * 4 + 1] = a1;
    att4[i * 4 + 2] = b0;
    att4[i * 4 + 3] = b1;
}

extern "C" void kernel_launch(void* const* d_in, const int* in_sizes, int n_in,
                              void* d_out, int out_size) {
    const float* x  = (const float*)d_in[0];
    const float* Wq = (const float*)d_in[1];
    const float* bq = (const float*)d_in[2];
    const float* Wk = (const float*)d_in[3];
    const float* bk = (const float*)d_in[4];
    const float* Wv = (const float*)d_in[5];
    const float* bv = (const float*)d_in[6];
    const int* edge = (const int*)d_in[7];

    float* out   = (float*)d_out;
    float* att   = out;                                   // [E, 8]
    float* v_out = out + (size_t)N_EDGES * D_HEAD;        // [N, 64]
    float* prods = v_out + (size_t)N_NODES * D_ATT;       // [E, 8]

    const int* e0 = edge;            // edge[0, :]
    const int* e1 = edge + N_EDGES;  // edge[1, :]

    const int smem_bytes = (3 * 64 * WT_STRIDE + 32 * XS_STRIDE) * (int)sizeof(float);
    cudaFuncSetAttribute(proj_kernel, cudaFuncAttributeMaxDynamicSharedMemorySize,
                         smem_bytes);

    proj_kernel<<<(N_NODES + 31) / 32, dim3(64, 4), smem_bytes>>>(
        x, Wq, bq, Wk, bk, Wv, bv, v_out);
    edge_kernel<<<N_EDGES * 8 / 256, 256>>>(e0, e1, att, prods);
    norm_kernel<<<(N_EDGES / 2 + 255) / 256, 256>>>(e1, att);
}

// round 8
// speedup vs baseline: 1.1984x; 1.1984x over previous
#include <cuda_runtime.h>

#define N_NODES 50000
#define N_EDGES 800000
#define IN_F 64
#define D_ATT 64
#define HEADS 8
#define D_HEAD 8

typedef unsigned long long ull;

// Scratch (device globals — no allocation allowed).
// g_q / g_k are stored TRANSPOSED within each 64-wide row: [node][d*8 + h],
// so each head-dim d's 8 values are contiguous (one 32B span).
__device__ __align__(16) float g_q[N_NODES * D_ATT];
__device__ __align__(16) float g_k[N_NODES * D_ATT];
__device__ __align__(16) float g_sum[N_NODES * D_HEAD];
// k-pair-interleaved weights: g_wp[mat][k2*64 + c] = (W[2k2][c], W[2k2+1][c])
__device__ __align__(16) float2 g_wp[3][32 * 64];

// ---------- f32x2 helpers (sm_103a packed FFMA2) ----------
__device__ __forceinline__ void unpack2(ull v, float& lo, float& hi) {
    asm("mov.b64 {%0, %1}, %2;" : "=f"(lo), "=f"(hi) : "l"(v));
}
__device__ __forceinline__ ull fma2(ull a, ull b, ull c) {
    ull d;
    asm("fma.rn.f32x2 %0, %1, %2, %3;" : "=l"(d) : "l"(a), "l"(b), "l"(c));
    return d;
}
__device__ __forceinline__ ull f2u(float2 v) {
    ull r;
    asm("mov.b64 %0, {%1, %2};" : "=l"(r) : "f"(v.x), "f"(v.y));
    return r;
}

// Interleave W into k-pair float2 layout (runs once, ~2us).
__global__ void prep_kernel(const float* __restrict__ Wq,
                            const float* __restrict__ Wk,
                            const float* __restrict__ Wv) {
    int i = blockIdx.x * blockDim.x + threadIdx.x;  // 0..6143
    if (i >= 3 * 32 * 64) return;
    int mat = i >> 11, r = i & 2047;
    int k2 = r >> 6, c = r & 63;
    const float* W = (mat == 0) ? Wq : (mat == 1) ? Wk : Wv;
    g_wp[mat][r] = make_float2(W[(2 * k2) * D_ATT + c], W[(2 * k2 + 1) * D_ATT + c]);
}

#define XS_STRIDE 66   // padded row stride (floats) for x tile

// Fused Q/K/V projection (+ zeroing of g_sum).
// Block = (64, 4) threads covering 32 rows. x staged row-major in smem;
// weights read as k-pair float2 from L1-resident global scratch (contiguous
// lanes -> 2 lines/warp). Accumulators are f32x2 packed over the k axis.
// Thread column = tx (contiguous weight loads, coalesced v store); the
// head-transpose permutation is applied at the q/k STORE index (still one
// 256B row per warp -> coalesced).
__global__ void __launch_bounds__(256)
proj_kernel(const float* __restrict__ x,
            const float* __restrict__ bq, const float* __restrict__ bk,
            const float* __restrict__ bv, float* __restrict__ v_out) {
    __shared__ float xs[32][XS_STRIDE];
    const int tx = threadIdx.x;      // 0..63 = original output column
    const int rg = threadIdx.y;      // 0..3
    const int row0 = blockIdx.x * 32;
    const int tid = rg * 64 + tx;
    const int pc = ((tx & 7) << 3) | (tx >> 3);  // transposed position of col tx

    // Zero this block's slice of g_sum (1563 blocks x 256 >= 400000 entries)
    {
        int zi = blockIdx.x * 256 + tid;
        if (zi < N_NODES * D_HEAD) g_sum[zi] = 0.0f;
    }

    // Stage x tile row-major (coalesced read)
    for (int i = tid; i < 32 * IN_F; i += 256) {
        int r = i >> 6, kk = i & 63;
        int grow = row0 + r;
        xs[r][kk] = (grow < N_NODES) ? x[grow * IN_F + kk] : 0.0f;
    }
    __syncthreads();

    ull aq[8], ak[8], av[8];
#pragma unroll
    for (int i = 0; i < 8; i++) { aq[i] = 0ull; ak[i] = 0ull; av[i] = 0ull; }

    const float2* wq_p = &g_wp[0][tx];
    const float2* wk_p = &g_wp[1][tx];
    const float2* wv_p = &g_wp[2][tx];
    const float* x_base = &xs[rg * 8][0];

#pragma unroll 4
    for (int kk2 = 0; kk2 < IN_F / 2; kk2++) {
        ull wq2 = f2u(__ldg(&wq_p[kk2 * 64]));   // LDG.64, lanes contiguous
        ull wk2 = f2u(__ldg(&wk_p[kk2 * 64]));
        ull wv2 = f2u(__ldg(&wv_p[kk2 * 64]));
#pragma unroll
        for (int i = 0; i < 8; i++) {
            ull x2 = *(const ull*)&x_base[i * XS_STRIDE + 2 * kk2];  // broadcast LDS.64
            aq[i] = fma2(x2, wq2, aq[i]);
            ak[i] = fma2(x2, wk2, ak[i]);
            av[i] = fma2(x2, wv2, av[i]);
        }
    }

    const float bqv = __ldg(&bq[tx]), bkv = __ldg(&bk[tx]), bvv = __ldg(&bv[tx]);
#pragma unroll
    for (int i = 0; i < 8; i++) {
        int r = row0 + rg * 8 + i;
        if (r < N_NODES) {
            float lo, hi;
            unpack2(aq[i], lo, hi);
            g_q[r * D_ATT + pc] = lo + hi + bqv;
            unpack2(ak[i], lo, hi);
            g_k[r * D_ATT + pc] = lo + hi + bkv;
            unpack2(av[i], lo, hi);
            v_out[r * D_ATT + tx] = lo + hi + bvv;
        }
    }
}

// Cooperative edge kernel: 8 lanes per edge.
// Lane j loads the CONTIGUOUS float4 at byte offset j*16 of the q/k rows
// (one 128B line per LDG.128 per edge). Elements j*4..j*4+3 all belong to
// head-dim d = j>>1: 4-wide partial dot + one shfl_xor(1) finishes each dot.
// Lane j then owns one (d, exp): 1 exp, 1 prods store, 1 att store per lane.
// Four shuffles gather the 8 exps into lanes 0/1, which issue two
// red.global.add.v4.f32 into g_sum. Max-subtraction omitted: softmax ratio is
// shift-invariant; logits ~N(0,3) cannot overflow fp32 exp.
__global__ void edge_kernel(const int* __restrict__ e0, const int* __restrict__ e1,
                            float* __restrict__ att_out, float* __restrict__ prods_out) {
    const int idx = blockIdx.x * blockDim.x + threadIdx.x;  // grid exact: N_EDGES*8
    const int e = idx >> 3;
    const int lane = threadIdx.x & 31;
    const int j = lane & 7;
    const int grp = lane & ~7;

    const int s = e0[e];
    const int t = e1[e];

    const float4* qp = (const float4*)(g_q + s * D_ATT);
    const float4* kp = (const float4*)(g_k + t * D_ATT);
    float4 q0 = qp[j];
    float4 q1 = qp[8 + j];
    float4 k0 = kp[j];
    float4 k1 = kp[8 + j];

    float p0 = q0.x * k0.x;
    p0 = fmaf(q0.y, k0.y, p0);
    p0 = fmaf(q0.z, k0.z, p0);
    p0 = fmaf(q0.w, k0.w, p0);
    float p1 = q1.x * k1.x;
    p1 = fmaf(q1.y, k1.y, p1);
    p1 = fmaf(q1.z, k1.z, p1);
    p1 = fmaf(q1.w, k1.w, p1);

    p0 += __shfl_xor_sync(0xffffffffu, p0, 1);
    p1 += __shfl_xor_sync(0xffffffffu, p1, 1);

    const float c = 0.35355339059327373f;  // 1/sqrt(8)
    const int m = j >> 1;
    const int odd = j & 1;
    const int d = odd ? (4 + m) : m;
    const float p = (odd ? p1 : p0) * c;

    const int oidx = e * D_HEAD + d;
    prods_out[oidx] = p;
    const float ex = __expf(p);
    att_out[oidx] = ex;

    float r0 = __shfl_sync(0xffffffffu, ex, grp + odd);
    float r1 = __shfl_sync(0xffffffffu, ex, grp + odd + 2);
    float r2 = __shfl_sync(0xffffffffu, ex, grp + odd + 4);
    float r3 = __shfl_sync(0xffffffffu, ex, grp + odd + 6);
    if (j < 2) {
        float* dst = &g_sum[t * D_HEAD + j * 4];  // 16B aligned
        asm volatile("red.global.add.v4.f32 [%0], {%1, %2, %3, %4};"
                     :: "l"(dst), "f"(r0), "f"(r1), "f"(r2), "f"(r3)
                     : "memory");
    }
}

// Two adjacent edges per thread: int2 index load, 4 independent sum-gather
// LDG.128 in flight.
__global__ void norm_kernel(const int* __restrict__ e1, float* __restrict__ att) {
    int i = blockIdx.x * blockDim.x + threadIdx.x;
    if (i >= N_EDGES / 2) return;
    int2 tt = ((const int2*)e1)[i];
    float4* att4 = (float4*)att;
    const float4* sum4 = (const float4*)g_sum;
    float4 sa0 = sum4[tt.x * 2], sa1 = sum4[tt.x * 2 + 1];
    float4 sb0 = sum4[tt.y * 2], sb1 = sum4[tt.y * 2 + 1];
    float4 a0 = att4[i * 4 + 0], a1 = att4[i * 4 + 1];
    float4 b0 = att4[i * 4 + 2], b1 = att4[i * 4 + 3];
    a0.x = __fdividef(a0.x, sa0.x + 1e-16f);
    a0.y = __fdividef(a0.y, sa0.y + 1e-16f);
    a0.z = __fdividef(a0.z, sa0.z + 1e-16f);
    a0.w = __fdividef(a0.w, sa0.w + 1e-16f);
    a1.x = __fdividef(a1.x, sa1.x + 1e-16f);
    a1.y = __fdividef(a1.y, sa1.y + 1e-16f);
    a1.z = __fdividef(a1.z, sa1.z + 1e-16f);
    a1.w = __fdividef(a1.w, sa1.w + 1e-16f);
    b0.x = __fdividef(b0.x, sb0.x + 1e-16f);
    b0.y = __fdividef(b0.y, sb0.y + 1e-16f);
    b0.z = __fdividef(b0.z, sb0.z + 1e-16f);
    b0.w = __fdividef(b0.w, sb0.w + 1e-16f);
    b1.x = __fdividef(b1.x, sb1.x + 1e-16f);
    b1.y = __fdividef(b1.y, sb1.y + 1e-16f);
    b1.z = __fdividef(b1.z, sb1.z + 1e-16f);
    b1.w = __fdividef(b1.w, sb1.w + 1e-16f);
    att4[i * 4 + 0] = a0;
    att4[i * 4 + 1] = a1;
    att4[i * 4 + 2] = b0;
    att4[i * 4 + 3] = b1;
}

extern "C" void kernel_launch(void* const* d_in, const int* in_sizes, int n_in,
                              void* d_out, int out_size) {
    const float* x  = (const float*)d_in[0];
    const float* Wq = (const float*)d_in[1];
    const float* bq = (const float*)d_in[2];
    const float* Wk = (const float*)d_in[3];
    const float* bk = (const float*)d_in[4];
    const float* Wv = (const float*)d_in[5];
    const float* bv = (const float*)d_in[6];
    const int* edge = (const int*)d_in[7];

    float* out   = (float*)d_out;
    float* att   = out;                                   // [E, 8]
    float* v_out = out + (size_t)N_EDGES * D_HEAD;        // [N, 64]
    float* prods = v_out + (size_t)N_NODES * D_ATT;       // [E, 8]

    const int* e0 = edge;            // edge[0, :]
    const int* e1 = edge + N_EDGES;  // edge[1, :]

    prep_kernel<<<(3 * 32 * 64 + 255) / 256, 256>>>(Wq, Wk, Wv);
    proj_kernel<<<(N_NODES + 31) / 32, dim3(64, 4)>>>(x, bq, bk, bv, v_out);
    edge_kernel<<<N_EDGES * 8 / 256, 256>>>(e0, e1, att, prods);
    norm_kernel<<<(N_EDGES / 2 + 255) / 256, 256>>>(e1, att);
}

// round 9
// speedup vs baseline: 1.4075x; 1.1745x over previous
#include <cuda_runtime.h>

#define N_NODES 50000
#define N_EDGES 800000
#define IN_F 64
#define D_ATT 64
#define HEADS 8
#define D_HEAD 8

typedef unsigned long long ull;

// Scratch (device globals — no allocation allowed).
// g_q / g_k are stored TRANSPOSED within each 64-wide row: [node][d*8 + h],
// so each head-dim d's 8 values are contiguous (one 32B span).
__device__ __align__(16) float g_q[N_NODES * D_ATT];
__device__ __align__(16) float g_k[N_NODES * D_ATT];
__device__ __align__(16) float g_sum[N_NODES * D_HEAD];
// k-pair-interleaved weights: g_wp[mat][k2*64 + c] = (W[2k2][c], W[2k2+1][c])
__device__ __align__(16) float2 g_wp[3][32 * 64];

// ---------- f32x2 helpers (sm_103a packed FFMA2) ----------
__device__ __forceinline__ void unpack2(ull v, float& lo, float& hi) {
    asm("mov.b64 {%0, %1}, %2;" : "=f"(lo), "=f"(hi) : "l"(v));
}
__device__ __forceinline__ ull fma2(ull a, ull b, ull c) {
    ull d;
    asm("fma.rn.f32x2 %0, %1, %2, %3;" : "=l"(d) : "l"(a), "l"(b), "l"(c));
    return d;
}
__device__ __forceinline__ ull f2u(float2 v) {
    ull r;
    asm("mov.b64 %0, {%1, %2};" : "=l"(r) : "f"(v.x), "f"(v.y));
    return r;
}

// Interleave W into k-pair float2 layout (runs once, ~2us).
__global__ void prep_kernel(const float* __restrict__ Wq,
                            const float* __restrict__ Wk,
                            const float* __restrict__ Wv) {
    int i = blockIdx.x * blockDim.x + threadIdx.x;  // 0..6143
    if (i >= 3 * 32 * 64) return;
    int mat = i >> 11, r = i & 2047;
    int k2 = r >> 6, c = r & 63;
    const float* W = (mat == 0) ? Wq : (mat == 1) ? Wk : Wv;
    g_wp[mat][r] = make_float2(W[(2 * k2) * D_ATT + c], W[(2 * k2 + 1) * D_ATT + c]);
}

#define XS_STRIDE 66      // padded row stride (floats) for x tile
#define PROJ_GRID 592     // 4 blocks/SM * 148 SMs: persistent multi-tile
#define N_TILES ((N_NODES + 31) / 32)

// Fused Q/K/V projection (+ zeroing of g_sum).
// Persistent blocks grid-stride over 32-row tiles (no wave-quantization tail).
// Block = (64, 4) threads. x staged row-major in smem; weights read as k-pair
// float2 from L1-resident global scratch (contiguous lanes -> 2 lines/warp).
// Accumulators are f32x2 packed over the k axis (horizontal add at the end).
// Thread column = tx (contiguous weight loads, coalesced v store); the
// head-transpose permutation is applied at the q/k STORE index (still one
// 256B row per warp -> coalesced).
__global__ void __launch_bounds__(256, 3)
proj_kernel(const float* __restrict__ x,
            const float* __restrict__ bq, const float* __restrict__ bk,
            const float* __restrict__ bv, float* __restrict__ v_out) {
    __shared__ float xs[32][XS_STRIDE];
    const int tx = threadIdx.x;      // 0..63 = original output column
    const int rg = threadIdx.y;      // 0..3
    const int tid = rg * 64 + tx;
    const int pc = ((tx & 7) << 3) | (tx >> 3);  // transposed position of col tx

    // Zero g_sum (grid-stride)
    for (int zi = blockIdx.x * 256 + tid; zi < N_NODES * D_HEAD; zi += PROJ_GRID * 256)
        g_sum[zi] = 0.0f;

    const float2* wq_p = &g_wp[0][tx];
    const float2* wk_p = &g_wp[1][tx];
    const float2* wv_p = &g_wp[2][tx];
    const float bqv = __ldg(&bq[tx]), bkv = __ldg(&bk[tx]), bvv = __ldg(&bv[tx]);

    for (int tile = blockIdx.x; tile < N_TILES; tile += PROJ_GRID) {
        const int row0 = tile * 32;
        __syncthreads();  // xs from previous tile fully consumed
        // Stage x tile row-major (coalesced read)
        for (int i = tid; i < 32 * IN_F; i += 256) {
            int r = i >> 6, kk = i & 63;
            int grow = row0 + r;
            xs[r][kk] = (grow < N_NODES) ? x[grow * IN_F + kk] : 0.0f;
        }
        __syncthreads();

        ull aq[8], ak[8], av[8];
#pragma unroll
        for (int i = 0; i < 8; i++) { aq[i] = 0ull; ak[i] = 0ull; av[i] = 0ull; }

        const float* x_base = &xs[rg * 8][0];

#pragma unroll 8
        for (int kk2 = 0; kk2 < IN_F / 2; kk2++) {
            ull wq2 = f2u(__ldg(&wq_p[kk2 * 64]));   // LDG.64, lanes contiguous
            ull wk2 = f2u(__ldg(&wk_p[kk2 * 64]));
            ull wv2 = f2u(__ldg(&wv_p[kk2 * 64]));
#pragma unroll
            for (int i = 0; i < 8; i++) {
                ull x2 = *(const ull*)&x_base[i * XS_STRIDE + 2 * kk2];  // bcast LDS.64
                aq[i] = fma2(x2, wq2, aq[i]);
                ak[i] = fma2(x2, wk2, ak[i]);
                av[i] = fma2(x2, wv2, av[i]);
            }
        }

#pragma unroll
        for (int i = 0; i < 8; i++) {
            int r = row0 + rg * 8 + i;
            if (r < N_NODES) {
                float lo, hi;
                unpack2(aq[i], lo, hi);
                g_q[r * D_ATT + pc] = lo + hi + bqv;
                unpack2(ak[i], lo, hi);
                g_k[r * D_ATT + pc] = lo + hi + bkv;
                unpack2(av[i], lo, hi);
                v_out[r * D_ATT + tx] = lo + hi + bvv;
            }
        }
    }
}

// Cooperative edge kernel: 8 lanes per edge.
// Lane j loads the CONTIGUOUS float4 at byte offset j*16 of the q/k rows
// (one 128B line per LDG.128 per edge). Elements j*4..j*4+3 all belong to
// head-dim d = j>>1: 4-wide partial dot + one shfl_xor(1) finishes each dot.
// Lane j then owns one (d, exp): 1 exp, 1 prods store, 1 att store per lane.
// Four shuffles gather the 8 exps into lanes 0/1, which issue two
// red.global.add.v4.f32 into g_sum. Max-subtraction omitted: softmax ratio is
// shift-invariant; logits ~N(0,3) cannot overflow fp32 exp.
__global__ void edge_kernel(const int* __restrict__ e0, const int* __restrict__ e1,
                            float* __restrict__ att_out, float* __restrict__ prods_out) {
    const int idx = blockIdx.x * blockDim.x + threadIdx.x;  // grid exact: N_EDGES*8
    const int e = idx >> 3;
    const int lane = threadIdx.x & 31;
    const int j = lane & 7;
    const int grp = lane & ~7;

    const int s = e0[e];
    const int t = e1[e];

    const float4* qp = (const float4*)(g_q + s * D_ATT);
    const float4* kp = (const float4*)(g_k + t * D_ATT);
    float4 q0 = qp[j];
    float4 q1 = qp[8 + j];
    float4 k0 = kp[j];
    float4 k1 = kp[8 + j];

    float p0 = q0.x * k0.x;
    p0 = fmaf(q0.y, k0.y, p0);
    p0 = fmaf(q0.z, k0.z, p0);
    p0 = fmaf(q0.w, k0.w, p0);
    float p1 = q1.x * k1.x;
    p1 = fmaf(q1.y, k1.y, p1);
    p1 = fmaf(q1.z, k1.z, p1);
    p1 = fmaf(q1.w, k1.w, p1);

    p0 += __shfl_xor_sync(0xffffffffu, p0, 1);
    p1 += __shfl_xor_sync(0xffffffffu, p1, 1);

    const float c = 0.35355339059327373f;  // 1/sqrt(8)
    const int m = j >> 1;
    const int odd = j & 1;
    const int d = odd ? (4 + m) : m;
    const float p = (odd ? p1 : p0) * c;

    const int oidx = e * D_HEAD + d;
    prods_out[oidx] = p;
    const float ex = __expf(p);
    att_out[oidx] = ex;

    float r0 = __shfl_sync(0xffffffffu, ex, grp + odd);
    float r1 = __shfl_sync(0xffffffffu, ex, grp + odd + 2);
    float r2 = __shfl_sync(0xffffffffu, ex, grp + odd + 4);
    float r3 = __shfl_sync(0xffffffffu, ex, grp + odd + 6);
    if (j < 2) {
        float* dst = &g_sum[t * D_HEAD + j * 4];  // 16B aligned
        asm volatile("red.global.add.v4.f32 [%0], {%1, %2, %3, %4};"
                     :: "l"(dst), "f"(r0), "f"(r1), "f"(r2), "f"(r3)
                     : "memory");
    }
}

// One thread per edge, fully vectorized (fastest measured variant: 14.9us).
__global__ void norm_kernel(const int* __restrict__ e1, float* __restrict__ att) {
    int e = blockIdx.x * blockDim.x + threadIdx.x;
    if (e >= N_EDGES) return;
    int t = e1[e];
    float4* att4 = (float4*)att;
    const float4* sum4 = (const float4*)g_sum;
    float4 a0 = att4[e * 2], a1 = att4[e * 2 + 1];
    float4 s0 = sum4[t * 2], s1 = sum4[t * 2 + 1];
    a0.x = __fdividef(a0.x, s0.x + 1e-16f);
    a0.y = __fdividef(a0.y, s0.y + 1e-16f);
    a0.z = __fdividef(a0.z, s0.z + 1e-16f);
    a0.w = __fdividef(a0.w, s0.w + 1e-16f);
    a1.x = __fdividef(a1.x, s1.x + 1e-16f);
    a1.y = __fdividef(a1.y, s1.y + 1e-16f);
    a1.z = __fdividef(a1.z, s1.z + 1e-16f);
    a1.w = __fdividef(a1.w, s1.w + 1e-16f);
    att4[e * 2] = a0;
    att4[e * 2 + 1] = a1;
}

extern "C" void kernel_launch(void* const* d_in, const int* in_sizes, int n_in,
                              void* d_out, int out_size) {
    const float* x  = (const float*)d_in[0];
    const float* Wq = (const float*)d_in[1];
    const float* bq = (const float*)d_in[2];
    const float* Wk = (const float*)d_in[3];
    const float* bk = (const float*)d_in[4];
    const float* Wv = (const float*)d_in[5];
    const float* bv = (const float*)d_in[6];
    const int* edge = (const int*)d_in[7];

    float* out   = (float*)d_out;
    float* att   = out;                                   // [E, 8]
    float* v_out = out + (size_t)N_EDGES * D_HEAD;        // [N, 64]
    float* prods = v_out + (size_t)N_NODES * D_ATT;       // [E, 8]

    const int* e0 = edge;            // edge[0, :]
    const int* e1 = edge + N_EDGES;  // edge[1, :]

    prep_kernel<<<(3 * 32 * 64 + 255) / 256, 256>>>(Wq, Wk, Wv);
    proj_kernel<<<PROJ_GRID, dim3(64, 4)>>>(x, bq, bk, bv, v_out);
    edge_kernel<<<N_EDGES * 8 / 256, 256>>>(e0, e1, att, prods);
    norm_kernel<<<(N_EDGES + 255) / 256, 256>>>(e1, att);
}